// round 15
// baseline (speedup 1.0000x reference)
#include <cuda_runtime.h>
#include <cstdint>

#define BB 2048
#define TT 512
#define KK 32
#define FULLM 0xffffffffu

// 128 MB alpha-row scratch + last-tag handoff (device globals; no allocation)
__device__ float g_alpha[(size_t)BB * TT * KK];
__device__ int   g_last[BB];

// ---- packed f32x2 helpers
__device__ __forceinline__ unsigned long long add2(unsigned long long a, unsigned long long b) {
    unsigned long long r; asm("add.rn.f32x2 %0,%1,%2;" : "=l"(r) : "l"(a), "l"(b)); return r;
}
__device__ __forceinline__ unsigned long long fma2(unsigned long long a, unsigned long long b, unsigned long long c) {
    unsigned long long r; asm("fma.rn.f32x2 %0,%1,%2,%3;" : "=l"(r) : "l"(a), "l"(b), "l"(c)); return r;
}
__device__ __forceinline__ float2 unpk(unsigned long long a) {
    float2 f; asm("mov.b64 {%0,%1},%2;" : "=f"(f.x), "=f"(f.y) : "l"(a)); return f;
}
__device__ __forceinline__ unsigned long long pk(float x, float y) {
    unsigned long long r; asm("mov.b64 %0,{%1,%2};" : "=l"(r) : "f"(x), "f"(y)); return r;
}

__device__ __forceinline__ float wsum(float v) {
#pragma unroll
    for (int o = 16; o; o >>= 1)
        v += __shfl_xor_sync(FULLM, v, o);
    return v;
}

// max_i (row[i] + trc[i][lane]) using packed adds
__device__ __forceinline__ float rowmax(const float* __restrict__ row,
                                        const unsigned long long* __restrict__ trc2) {
    const ulonglong2* r2 = reinterpret_cast<const ulonglong2*>(row);
    float best = -3.402823466e38f;
#pragma unroll
    for (int c = 0; c < 4; c++) {
        ulonglong2 qa = r2[c];
        ulonglong2 qb = r2[c + 4];
        float2 f0 = unpk(add2(qa.x, trc2[2 * c + 0]));
        float2 f1 = unpk(add2(qa.y, trc2[2 * c + 1]));
        float2 f2 = unpk(add2(qb.x, trc2[2 * c + 8]));
        float2 f3 = unpk(add2(qb.y, trc2[2 * c + 9]));
        float m0 = fmaxf(fmaxf(f0.x, f0.y), fmaxf(f1.x, f1.y));
        float m1 = fmaxf(fmaxf(f2.x, f2.y), fmaxf(f3.x, f3.y));
        best = fmaxf(best, fmaxf(m0, m1));
    }
    return best;
}

// sum_i row[i] * etr[i][lane] using packed FMAs
__device__ __forceinline__ float rowdot(const float* __restrict__ row,
                                        const unsigned long long* __restrict__ etr2) {
    const ulonglong2* r2 = reinterpret_cast<const ulonglong2*>(row);
    unsigned long long a0 = 0ull, a1 = 0ull, a2 = 0ull, a3 = 0ull;
#pragma unroll
    for (int c = 0; c < 4; c++) {
        ulonglong2 qa = r2[c];
        ulonglong2 qb = r2[c + 4];
        a0 = fma2(qa.x, etr2[2 * c + 0], a0);
        a1 = fma2(qa.y, etr2[2 * c + 1], a1);
        a2 = fma2(qb.x, etr2[2 * c + 8], a2);
        a3 = fma2(qb.y, etr2[2 * c + 9], a3);
    }
    float2 s = unpk(add2(add2(a0, a1), add2(a2, a3)));
    return s.x + s.y;
}

// exact power-of-2 renormalization (shfl exponent max)
__device__ __forceinline__ void renorm(float& a, int& C) {
    int eb = (__float_as_int(a) >> 23) & 0xff;
#pragma unroll
    for (int o = 16; o; o >>= 1)
        eb = max(eb, __shfl_xor_sync(FULLM, eb, o));
    int de = eb - 127;
    C += de;
    a *= __int_as_float((127 - de) << 23);
}

__device__ __forceinline__ uint32_t smem_u32(const void* p) {
    uint32_t a;
    asm("{ .reg .u64 t; cvta.to.shared.u64 t, %1; cvt.u32.u64 %0, t; }" : "=r"(a) : "l"(p));
    return a;
}

// =============================== Kernel 1: forward passes ===============================
__global__ __launch_bounds__(64, 16)
void crf_forward_kernel(const float* __restrict__ pot,     // [B,T,K]
                        const float* __restrict__ trans,   // [K,K]
                        const int*   __restrict__ seqlen,  // [B]
                        const int*   __restrict__ tags_in, // [B,T]
                        float*       __restrict__ out)     // [B*T + 2B] f32
{
    __shared__ float Trp[KK * 33];                   // trans for seq-score (partition warp only)
    __shared__ __align__(16) float vrow[2][KK];
    __shared__ __align__(16) float lrow[2][KK];

    const int tid  = threadIdx.x;
    const int lane = tid & 31;
    const int role = tid >> 5;          // 0 = viterbi fwd, 1 = partition
    const int b    = blockIdx.x;
    const int len  = seqlen[b];

    const float LOG2E = 1.4426950408889634f;
    const float* pb = pot + (size_t)b * TT * KK;
    float* out_tags = out;

    if (role == 0) {
        // ---------------- Viterbi forward (value-only; alphas streamed) ----------------
        unsigned long long trc2[16];
#pragma unroll
        for (int k = 0; k < 16; k++)
            trc2[k] = pk(__ldg(&trans[(2 * k) * KK + lane]),
                         __ldg(&trans[(2 * k + 1) * KK + lane]));

        float* gab = g_alpha + (size_t)b * TT * KK;
        float alpha = pb[lane];

        // 8-deep pot prefetch pipeline (fully unrolled: pr[] stays in regs)
        float pr[8];
#pragma unroll
        for (int d = 0; d < 8; d++) {
            int tq = 1 + d;
            pr[d] = (tq < len) ? __ldg(&pb[(size_t)tq * KK + lane]) : 0.f;
        }

        int t = 1;
        while (t < len) {
#pragma unroll
            for (int d = 0; d < 8; d++) {
                if (t < len) {                       // warp-uniform
                    float p = pr[d];
                    int tf = t + 8;
                    pr[d] = (tf < len) ? __ldg(&pb[(size_t)tf * KK + lane]) : 0.f;
                    gab[(size_t)(t - 1) * KK + lane] = alpha;
                    vrow[d & 1][lane] = alpha;
                    __syncwarp();
                    alpha = p + rowmax(vrow[d & 1], trc2);
                    t++;
                }
            }
        }

        // last_tag / best_score: bundled shfl argmax (first-occurrence exact)
        float bv = alpha; int bi = lane;
#pragma unroll
        for (int o = 16; o; o >>= 1) {
            float ov = __shfl_xor_sync(FULLM, bv, o);
            int   oi = __shfl_xor_sync(FULLM, bi, o);
            if (ov > bv || (ov == bv && oi < bi)) { bv = ov; bi = oi; }
        }
        const int last_tag = bi;

        for (int tt = len - 1 + lane; tt < TT; tt += 32)
            out_tags[(size_t)b * TT + tt] = (float)last_tag;
        if (lane == 0) {
            out[(size_t)BB * TT + b] = bv;   // best_score
            g_last[b] = last_tag;            // handoff to backtrace kernel
        }
    } else {
        // ---------------- partition (linear domain) + seq-score ----------------
        unsigned long long etr2[16];
#pragma unroll
        for (int k = 0; k < 16; k++)
            etr2[k] = pk(exp2f(__ldg(&trans[(2 * k) * KK + lane]) * LOG2E),
                         exp2f(__ldg(&trans[(2 * k + 1) * KK + lane]) * LOG2E));

        float a = exp2f(pb[lane] * LOG2E);
        int C = 0;

        // 8-deep prefetch of exp(pot) (MUFU hoisted off the chain)
        float pr[8];
#pragma unroll
        for (int d = 0; d < 8; d++) {
            int tq = 1 + d;
            pr[d] = (tq < len) ? exp2f(__ldg(&pb[(size_t)tq * KK + lane]) * LOG2E) : 0.f;
        }

        int t = 1;
        while (t < len) {
#pragma unroll
            for (int d = 0; d < 8; d++) {
                if (t < len) {                       // warp-uniform
                    float ep = pr[d];
                    int tf = t + 8;
                    pr[d] = (tf < len) ? exp2f(__ldg(&pb[(size_t)tf * KK + lane]) * LOG2E) : 0.f;
                    lrow[d & 1][lane] = a;
                    __syncwarp();
                    a = ep * rowdot(lrow[d & 1], etr2);
                    t++;
                    if ((t & 7) == 0)                // every 8 steps: exact 2^k rescale
                        renorm(a, C);
                }
            }
        }

        float s = wsum(a);
        float log_norm = (float)((double)C * 0.6931471805599453) + logf(s);

        // transitions into smem for seq-score (single-warp use; no block barrier needed)
        for (int idx = lane; idx < KK * KK; idx += 32)
            Trp[(idx >> 5) * 33 + (idx & 31)] = trans[idx];
        __syncwarp();

        const int* ti = tags_in + (size_t)b * TT;
        float sscore = 0.f;
        for (int tt = lane; tt < TT; tt += 32) {
            int tg = ti[tt];
            if (tt < len)     sscore += pb[(size_t)tt * KK + tg];
            if (tt < len - 1) sscore += Trp[tg * 33 + ti[tt + 1]];
        }
        sscore = wsum(sscore);

        if (lane == 0)
            out[(size_t)BB * TT + BB + b] = sscore - log_norm;
    }
}

// =============================== Kernel 2: batch-transposed backtrace ===============================
// One warp handles 8 sequences; 4 lanes per sequence. Alpha rows staged via cp.async (depth 3).
#define NSTG 4   // smem stage slots (3 in flight)

__global__ __launch_bounds__(32)
void crf_backtrace_kernel(const float* __restrict__ trans,
                          const int*   __restrict__ seqlen,
                          float*       __restrict__ out)
{
    __shared__ float Ttr[KK][36];                          // Ttr[j][i] = trans[i][j]
    __shared__ __align__(16) float buf[NSTG][8][8][36];    // [slot][step d][seq s][state i]

    const int lane  = threadIdx.x;
    const int sbase = blockIdx.x * 8;
    const int s = lane >> 2;                   // sequence-in-warp 0..7
    const int q = lane & 3;                    // candidate quarter 0..3
    const int seq = sbase + s;

    for (int idx = lane; idx < KK * KK; idx += 32) {
        int i = idx >> 5, j = idx & 31;
        Ttr[j][i] = trans[i * KK + j];
    }

    const int len = seqlen[seq];
    int jcur = g_last[seq];
    const int lim = len - 2;                   // last backtrace step for this seq

    int tmax = lim;
#pragma unroll
    for (int o = 16; o; o >>= 1)
        tmax = max(tmax, __shfl_xor_sync(FULLM, tmax, o));
    if (tmax < 0) return;                      // uniform: whole warp exits

    // issue one stage (8 rows x 8 seqs) via cp.async; ALWAYS commits exactly one group
    auto stage_issue = [&](int th, int ss) {
#pragma unroll
        for (int it = 0; it < 16; it++) {
            int c = it * 32 + lane;            // chunk 0..511
            int k   = c & 7;                   // 16B chunk within row
            int sdx = (c >> 3) & 7;            // seq
            int d   = c >> 6;                  // step 0..7
            int t = th - d;
            if (t >= 0) {
                const float* src = g_alpha + ((size_t)(sbase + sdx) * TT + t) * KK + k * 4;
                uint32_t dst = smem_u32(&buf[ss][d][sdx][k * 4]);
                asm volatile("cp.async.cg.shared.global [%0], [%1], 16;" :: "r"(dst), "l"(src));
            }
        }
        asm volatile("cp.async.commit_group;" ::: "memory");
    };

    const int nst = (tmax >> 3) + 1;           // number of stages

    // prologue: 3 committed groups (stages 0..2, empty commits beyond nst)
#pragma unroll
    for (int p = 0; p < 3; p++) {
        if (p < nst) stage_issue(tmax - 8 * p, p);
        else asm volatile("cp.async.commit_group;" ::: "memory");
    }

    for (int kst = 0; kst < nst; kst++) {
        int slot = kst & (NSTG - 1);
        // keep 3 groups in flight: issue stage kst+3 (slot reuse is safe: == slot of kst-1)
        if (kst + 3 < nst) stage_issue(tmax - 8 * (kst + 3), (kst + 3) & (NSTG - 1));
        else asm volatile("cp.async.commit_group;" ::: "memory");

        // after this, total groups = kst+4; wait_group 3 => stages <= kst complete
        asm volatile("cp.async.wait_group 3;" ::: "memory");
        __syncwarp();

#pragma unroll
        for (int d = 0; d < 8; d++) {
            int t = tmax - 8 * kst - d;
            if (t < 0) break;                  // warp-uniform (final stage only)

            const float* ar = &buf[slot][d][s][q * 8];
            const float* tr = &Ttr[jcur][q * 8];
            float v[8];
#pragma unroll
            for (int k = 0; k < 8; k++) v[k] = ar[k] + tr[k];
            float m0 = fmaxf(v[0], v[1]), m1 = fmaxf(v[2], v[3]);
            float m2 = fmaxf(v[4], v[5]), m3 = fmaxf(v[6], v[7]);
            float best = fmaxf(fmaxf(m0, m1), fmaxf(m2, m3));
            int idx = 0;
#pragma unroll
            for (int k = 7; k >= 0; k--)
                if (v[k] == best) idx = k;     // lowest k wins (first-occurrence)
            float vbest = best;
            int ibest = q * 8 + idx;

            // combine across the 4 lanes of this sequence (xor 1,2 stay in-group)
#pragma unroll
            for (int o = 1; o <= 2; o <<= 1) {
                float ov = __shfl_xor_sync(FULLM, vbest, o);
                int   oi = __shfl_xor_sync(FULLM, ibest, o);
                if (ov > vbest || (ov == vbest && oi < ibest)) { vbest = ov; ibest = oi; }
            }

            if (t <= lim) {                    // per-sequence predicate
                jcur = ibest;
                if (q == 0)
                    out[(size_t)seq * TT + t] = (float)jcur;
            }
        }
        __syncwarp();                          // slot consumed before refill next iters
    }
}

extern "C" void kernel_launch(void* const* d_in, const int* in_sizes, int n_in,
                              void* d_out, int out_size) {
    const float* pot    = (const float*)d_in[0];
    const float* trans  = (const float*)d_in[1];
    const int*   seqlen = (const int*)d_in[2];
    const int*   tags   = (const int*)d_in[3];
    float* out = (float*)d_out;

    crf_forward_kernel<<<BB, 64>>>(pot, trans, seqlen, tags, out);
    crf_backtrace_kernel<<<BB / 8, 32>>>(trans, seqlen, out);
}

// round 16
// speedup vs baseline: 1.5017x; 1.5017x over previous
#include <cuda_runtime.h>
#include <cstdint>

#define BB 2048
#define TT 512
#define KK 32
#define FULLM 0xffffffffu

// 128 MB alpha-row scratch + last-tag handoff (device globals; no allocation)
__device__ float g_alpha[(size_t)BB * TT * KK];
__device__ int   g_last[BB];

// ---- packed f32x2 helpers
__device__ __forceinline__ unsigned long long add2(unsigned long long a, unsigned long long b) {
    unsigned long long r; asm("add.rn.f32x2 %0,%1,%2;" : "=l"(r) : "l"(a), "l"(b)); return r;
}
__device__ __forceinline__ unsigned long long fma2(unsigned long long a, unsigned long long b, unsigned long long c) {
    unsigned long long r; asm("fma.rn.f32x2 %0,%1,%2,%3;" : "=l"(r) : "l"(a), "l"(b), "l"(c)); return r;
}
__device__ __forceinline__ float2 unpk(unsigned long long a) {
    float2 f; asm("mov.b64 {%0,%1},%2;" : "=f"(f.x), "=f"(f.y) : "l"(a)); return f;
}
__device__ __forceinline__ unsigned long long pk(float x, float y) {
    unsigned long long r; asm("mov.b64 %0,{%1,%2};" : "=l"(r) : "f"(x), "f"(y)); return r;
}

__device__ __forceinline__ float wsum(float v) {
#pragma unroll
    for (int o = 16; o; o >>= 1)
        v += __shfl_xor_sync(FULLM, v, o);
    return v;
}

// max_i (row[i] + trc[i][lane]) using packed adds
__device__ __forceinline__ float rowmax(const float* __restrict__ row,
                                        const unsigned long long* __restrict__ trc2) {
    const ulonglong2* r2 = reinterpret_cast<const ulonglong2*>(row);
    float best = -3.402823466e38f;
#pragma unroll
    for (int c = 0; c < 4; c++) {
        ulonglong2 qa = r2[c];
        ulonglong2 qb = r2[c + 4];
        float2 f0 = unpk(add2(qa.x, trc2[2 * c + 0]));
        float2 f1 = unpk(add2(qa.y, trc2[2 * c + 1]));
        float2 f2 = unpk(add2(qb.x, trc2[2 * c + 8]));
        float2 f3 = unpk(add2(qb.y, trc2[2 * c + 9]));
        float m0 = fmaxf(fmaxf(f0.x, f0.y), fmaxf(f1.x, f1.y));
        float m1 = fmaxf(fmaxf(f2.x, f2.y), fmaxf(f3.x, f3.y));
        best = fmaxf(best, fmaxf(m0, m1));
    }
    return best;
}

// sum_i row[i] * etr[i][lane] using packed FMAs
__device__ __forceinline__ float rowdot(const float* __restrict__ row,
                                        const unsigned long long* __restrict__ etr2) {
    const ulonglong2* r2 = reinterpret_cast<const ulonglong2*>(row);
    unsigned long long a0 = 0ull, a1 = 0ull, a2 = 0ull, a3 = 0ull;
#pragma unroll
    for (int c = 0; c < 4; c++) {
        ulonglong2 qa = r2[c];
        ulonglong2 qb = r2[c + 4];
        a0 = fma2(qa.x, etr2[2 * c + 0], a0);
        a1 = fma2(qa.y, etr2[2 * c + 1], a1);
        a2 = fma2(qb.x, etr2[2 * c + 8], a2);
        a3 = fma2(qb.y, etr2[2 * c + 9], a3);
    }
    float2 s = unpk(add2(add2(a0, a1), add2(a2, a3)));
    return s.x + s.y;
}

// exact power-of-2 renormalization (shfl exponent max)
__device__ __forceinline__ void renorm(float& a, int& C) {
    int eb = (__float_as_int(a) >> 23) & 0xff;
#pragma unroll
    for (int o = 16; o; o >>= 1)
        eb = max(eb, __shfl_xor_sync(FULLM, eb, o));
    int de = eb - 127;
    C += de;
    a *= __int_as_float((127 - de) << 23);
}

__device__ __forceinline__ uint32_t smem_u32(const void* p) {
    uint32_t a;
    asm("{ .reg .u64 t; cvta.to.shared.u64 t, %1; cvt.u32.u64 %0, t; }" : "=r"(a) : "l"(p));
    return a;
}

// =============================== Kernel 1: forward passes ===============================
__global__ __launch_bounds__(64, 16)
void crf_forward_kernel(const float* __restrict__ pot,     // [B,T,K]
                        const float* __restrict__ trans,   // [K,K]
                        const int*   __restrict__ seqlen,  // [B]
                        const int*   __restrict__ tags_in, // [B,T]
                        float*       __restrict__ out)     // [B*T + 2B] f32
{
    __shared__ float Trp[KK * 33];                   // trans for seq-score (partition warp only)
    __shared__ __align__(16) float vrow[2][KK];
    __shared__ __align__(16) float lrow[2][KK];

    const int tid  = threadIdx.x;
    const int lane = tid & 31;
    const int role = tid >> 5;          // 0 = viterbi fwd, 1 = partition
    const int b    = blockIdx.x;
    const int len  = seqlen[b];

    const float LOG2E = 1.4426950408889634f;
    const float* pb = pot + (size_t)b * TT * KK;
    float* out_tags = out;

    const int S    = len - 1;          // total recurrence steps (warp-uniform)
    const int nblk = S >> 3;           // full 8-step blocks
    const int tail = S & 7;

    if (role == 0) {
        // ---------------- Viterbi forward (value-only; alphas streamed) ----------------
        unsigned long long trc2[16];
#pragma unroll
        for (int k = 0; k < 16; k++)
            trc2[k] = pk(__ldg(&trans[(2 * k) * KK + lane]),
                         __ldg(&trans[(2 * k + 1) * KK + lane]));

        float* gab = g_alpha + (size_t)b * TT * KK;
        float alpha = pb[lane];

        // 8-deep pot prefetch (clamped indices: branchless, always in-bounds;
        // over-fetched rows are never consumed)
        float pr[8];
#pragma unroll
        for (int d = 0; d < 8; d++) {
            int tq = min(1 + d, TT - 1);
            pr[d] = __ldg(&pb[(size_t)tq * KK + lane]);
        }

        int t = 1;
        for (int blk = 0; blk < nblk; blk++) {
#pragma unroll
            for (int d = 0; d < 8; d++) {            // straight-line: no per-step branch
                float p = pr[d];
                int tf = min(t + 8, TT - 1);
                pr[d] = __ldg(&pb[(size_t)tf * KK + lane]);
                gab[(size_t)(t - 1) * KK + lane] = alpha;
                vrow[d & 1][lane] = alpha;
                __syncwarp();
                alpha = p + rowmax(vrow[d & 1], trc2);
                t++;
            }
        }
        for (int r = 0; r < tail; r++) {             // <=7 steps
            float p = pr[r];
            gab[(size_t)(t - 1) * KK + lane] = alpha;
            vrow[0][lane] = alpha;
            __syncwarp();
            alpha = p + rowmax(vrow[0], trc2);
            __syncwarp();
            t++;
        }

        // last_tag / best_score: bundled shfl argmax (first-occurrence exact)
        float bv = alpha; int bi = lane;
#pragma unroll
        for (int o = 16; o; o >>= 1) {
            float ov = __shfl_xor_sync(FULLM, bv, o);
            int   oi = __shfl_xor_sync(FULLM, bi, o);
            if (ov > bv || (ov == bv && oi < bi)) { bv = ov; bi = oi; }
        }
        const int last_tag = bi;

        for (int tt = len - 1 + lane; tt < TT; tt += 32)
            out_tags[(size_t)b * TT + tt] = (float)last_tag;
        if (lane == 0) {
            out[(size_t)BB * TT + b] = bv;   // best_score
            g_last[b] = last_tag;            // handoff to backtrace kernel
        }
    } else {
        // ---------------- partition (linear domain) + seq-score ----------------
        unsigned long long etr2[16];
#pragma unroll
        for (int k = 0; k < 16; k++)
            etr2[k] = pk(exp2f(__ldg(&trans[(2 * k) * KK + lane]) * LOG2E),
                         exp2f(__ldg(&trans[(2 * k + 1) * KK + lane]) * LOG2E));

        float a = exp2f(pb[lane] * LOG2E);
        int C = 0;

        // 8-deep prefetch of exp(pot) (MUFU hoisted off the chain)
        float pr[8];
#pragma unroll
        for (int d = 0; d < 8; d++) {
            int tq = min(1 + d, TT - 1);
            pr[d] = exp2f(__ldg(&pb[(size_t)tq * KK + lane]) * LOG2E);
        }

        int t = 1;
        for (int blk = 0; blk < nblk; blk++) {
#pragma unroll
            for (int d = 0; d < 8; d++) {            // straight-line: no per-step branch
                float ep = pr[d];
                int tf = min(t + 8, TT - 1);
                pr[d] = exp2f(__ldg(&pb[(size_t)tf * KK + lane]) * LOG2E);
                lrow[d & 1][lane] = a;
                __syncwarp();
                a = ep * rowdot(lrow[d & 1], etr2);
                t++;
            }
            renorm(a, C);                            // exact 2^k rescale, once per 8 steps
        }
        for (int r = 0; r < tail; r++) {             // <=7 steps (growth bounded, no renorm)
            float ep = pr[r];
            lrow[0][lane] = a;
            __syncwarp();
            a = ep * rowdot(lrow[0], etr2);
            __syncwarp();
            t++;
        }

        float s = wsum(a);
        float log_norm = (float)((double)C * 0.6931471805599453) + logf(s);

        // transitions into smem for seq-score (single-warp use; no block barrier needed)
        for (int idx = lane; idx < KK * KK; idx += 32)
            Trp[(idx >> 5) * 33 + (idx & 31)] = trans[idx];
        __syncwarp();

        const int* ti = tags_in + (size_t)b * TT;
        float sscore = 0.f;
        for (int tt = lane; tt < TT; tt += 32) {
            int tg = ti[tt];
            if (tt < len)     sscore += pb[(size_t)tt * KK + tg];
            if (tt < len - 1) sscore += Trp[tg * 33 + ti[tt + 1]];
        }
        sscore = wsum(sscore);

        if (lane == 0)
            out[(size_t)BB * TT + BB + b] = sscore - log_norm;
    }
}

// =============================== Kernel 2: batch-transposed backtrace ===============================
// One warp handles 8 sequences; 4 lanes per sequence. Alpha rows staged via cp.async (depth 3).
#define NSTG 4   // smem stage slots (3 in flight)

__global__ __launch_bounds__(32)
void crf_backtrace_kernel(const float* __restrict__ trans,
                          const int*   __restrict__ seqlen,
                          float*       __restrict__ out)
{
    __shared__ float Ttr[KK][36];                          // Ttr[j][i] = trans[i][j]
    __shared__ __align__(16) float buf[NSTG][8][8][36];    // [slot][step d][seq s][state i]

    const int lane  = threadIdx.x;
    const int sbase = blockIdx.x * 8;
    const int s = lane >> 2;                   // sequence-in-warp 0..7
    const int q = lane & 3;                    // candidate quarter 0..3
    const int seq = sbase + s;

    for (int idx = lane; idx < KK * KK; idx += 32) {
        int i = idx >> 5, j = idx & 31;
        Ttr[j][i] = trans[i * KK + j];
    }

    const int len = seqlen[seq];
    int jcur = g_last[seq];
    const int lim = len - 2;                   // last backtrace step for this seq

    int tmax = lim;
#pragma unroll
    for (int o = 16; o; o >>= 1)
        tmax = max(tmax, __shfl_xor_sync(FULLM, tmax, o));
    if (tmax < 0) return;                      // uniform: whole warp exits

    // issue one stage (8 rows x 8 seqs) via cp.async; ALWAYS commits exactly one group
    auto stage_issue = [&](int th, int ss) {
#pragma unroll
        for (int it = 0; it < 16; it++) {
            int c = it * 32 + lane;            // chunk 0..511
            int k   = c & 7;                   // 16B chunk within row
            int sdx = (c >> 3) & 7;            // seq
            int d   = c >> 6;                  // step 0..7
            int t = th - d;
            if (t >= 0) {
                const float* src = g_alpha + ((size_t)(sbase + sdx) * TT + t) * KK + k * 4;
                uint32_t dst = smem_u32(&buf[ss][d][sdx][k * 4]);
                asm volatile("cp.async.cg.shared.global [%0], [%1], 16;" :: "r"(dst), "l"(src));
            }
        }
        asm volatile("cp.async.commit_group;" ::: "memory");
    };

    const int nst = (tmax >> 3) + 1;           // number of stages

    // prologue: 3 committed groups (stages 0..2, empty commits beyond nst)
#pragma unroll
    for (int p = 0; p < 3; p++) {
        if (p < nst) stage_issue(tmax - 8 * p, p);
        else asm volatile("cp.async.commit_group;" ::: "memory");
    }

    for (int kst = 0; kst < nst; kst++) {
        int slot = kst & (NSTG - 1);
        // keep 3 groups in flight: issue stage kst+3 (slot reuse is safe: == slot of kst-1)
        if (kst + 3 < nst) stage_issue(tmax - 8 * (kst + 3), (kst + 3) & (NSTG - 1));
        else asm volatile("cp.async.commit_group;" ::: "memory");

        // after this, total groups = kst+4; wait_group 3 => stages <= kst complete
        asm volatile("cp.async.wait_group 3;" ::: "memory");
        __syncwarp();

#pragma unroll
        for (int d = 0; d < 8; d++) {
            int t = tmax - 8 * kst - d;
            if (t < 0) break;                  // warp-uniform (final stage only)

            const float* ar = &buf[slot][d][s][q * 8];
            const float* tr = &Ttr[jcur][q * 8];
            float v[8];
#pragma unroll
            for (int k = 0; k < 8; k++) v[k] = ar[k] + tr[k];
            float m0 = fmaxf(v[0], v[1]), m1 = fmaxf(v[2], v[3]);
            float m2 = fmaxf(v[4], v[5]), m3 = fmaxf(v[6], v[7]);
            float best = fmaxf(fmaxf(m0, m1), fmaxf(m2, m3));
            int idx = 0;
#pragma unroll
            for (int k = 7; k >= 0; k--)
                if (v[k] == best) idx = k;     // lowest k wins (first-occurrence)
            float vbest = best;
            int ibest = q * 8 + idx;

            // combine across the 4 lanes of this sequence (xor 1,2 stay in-group)
#pragma unroll
            for (int o = 1; o <= 2; o <<= 1) {
                float ov = __shfl_xor_sync(FULLM, vbest, o);
                int   oi = __shfl_xor_sync(FULLM, ibest, o);
                if (ov > vbest || (ov == vbest && oi < ibest)) { vbest = ov; ibest = oi; }
            }

            if (t <= lim) {                    // per-sequence predicate
                jcur = ibest;
                if (q == 0)
                    out[(size_t)seq * TT + t] = (float)jcur;
            }
        }
        __syncwarp();                          // slot consumed before refill next iters
    }
}

extern "C" void kernel_launch(void* const* d_in, const int* in_sizes, int n_in,
                              void* d_out, int out_size) {
    const float* pot    = (const float*)d_in[0];
    const float* trans  = (const float*)d_in[1];
    const int*   seqlen = (const int*)d_in[2];
    const int*   tags   = (const int*)d_in[3];
    float* out = (float*)d_out;

    crf_forward_kernel<<<BB, 64>>>(pot, trans, seqlen, tags, out);
    crf_backtrace_kernel<<<BB / 8, 32>>>(trans, seqlen, out);
}